// round 9
// baseline (speedup 1.0000x reference)
#include <cuda_runtime.h>
#include <math.h>

#define N_NODES 512
#define TDIM 288
#define LDIM 128
#define BBATCH 4
#define MROWS (BBATCH * N_NODES)   // 2048
#define XCOLS 256                  // combined X1|X2 columns

typedef unsigned long long u64;
typedef unsigned int u32;

// ---- packed f32x2 helpers (sm_100+) ----
__device__ __forceinline__ u64 add2(u64 a, u64 b) {
    u64 r; asm("add.rn.f32x2 %0,%1,%2;" : "=l"(r) : "l"(a), "l"(b)); return r;
}
__device__ __forceinline__ u64 fma2(u64 a, u64 b, u64 c) {
    u64 r; asm("fma.rn.f32x2 %0,%1,%2,%3;" : "=l"(r) : "l"(a), "l"(b), "l"(c)); return r;
}
__device__ __forceinline__ float lo32(u64 v) { return __uint_as_float((unsigned)(v & 0xffffffffu)); }
__device__ __forceinline__ float hi32(u64 v) { return __uint_as_float((unsigned)(v >> 32)); }
__device__ __forceinline__ u64 pack2(float x, float y) {
    return ((u64)__float_as_uint(y) << 32) | (u64)__float_as_uint(x);
}

// ---- tf32 helpers ----
__device__ __forceinline__ float to_tf32(float v) {
    u32 r; asm("cvt.rna.tf32.f32 %0,%1;" : "=r"(r) : "f"(v));
    return __uint_as_float(r);
}
__device__ __forceinline__ void mma_tf32(float* d, const u32* a, const u32* b) {
    asm("mma.sync.aligned.m16n8k8.row.col.f32.tf32.tf32.f32 "
        "{%0,%1,%2,%3}, {%4,%5,%6,%7}, {%8,%9}, {%0,%1,%2,%3};"
        : "+f"(d[0]), "+f"(d[1]), "+f"(d[2]), "+f"(d[3])
        : "r"(a[0]), "r"(a[1]), "r"(a[2]), "r"(a[3]), "r"(b[0]), "r"(b[1]));
}

// ---- cp.async helpers ----
__device__ __forceinline__ void cpa16(u32 s, const void* g) {
    asm volatile("cp.async.ca.shared.global [%0], [%1], 16;" :: "r"(s), "l"(g));
}
__device__ __forceinline__ void cp_commit() {
    asm volatile("cp.async.commit_group;");
}
template <int N> __device__ __forceinline__ void cp_wait() {
    asm volatile("cp.async.wait_group %0;" :: "n"(N));
}

// Scratch (device globals)
__device__ float g_xh[MROWS * TDIM];
__device__ float g_xl[MROWS * TDIM];
__device__ float g_wh[256 * TDIM];          // [W1;W2]
__device__ float g_wl[256 * TDIM];
__device__ float g_wph[2 * 128 * 128];      // [z][n][k]
__device__ float g_wpl[2 * 128 * 128];
__device__ float g_Xh[MROWS * XCOLS];       // leaky output, hi/lo
__device__ float g_Xl[MROWS * XCOLS];
__device__ float g_S1[MROWS * LDIM];
__device__ float g_S2P[MROWS * LDIM];

// ---------------------------------------------------------------------------
// Prep: split x, [W1;W2], Wp into tf32 hi/lo planes.
// ---------------------------------------------------------------------------
#define N_X  (MROWS * TDIM)        // 589824
#define N_W  (256 * TDIM)          // 73728
#define N_WP (2 * 128 * 128)       // 32768

__global__ __launch_bounds__(256)
void prep_split(const float* __restrict__ x,
                const float* __restrict__ W1, const float* __restrict__ W2,
                const float* __restrict__ Wp)
{
    int idx = blockIdx.x * 256 + threadIdx.x;
    int total = N_X + N_W + N_WP;
    if (idx >= total) return;
    float v; float* H; float* L; int o;
    if (idx < N_X) {
        v = x[idx]; H = g_xh; L = g_xl; o = idx;
    } else if (idx < N_X + N_W) {
        o = idx - N_X;
        int r = o / TDIM, k = o - r * TDIM;
        v = (r < 128) ? W1[r * TDIM + k] : W2[(r - 128) * TDIM + k];
        H = g_wh; L = g_wl;
    } else {
        o = idx - N_X - N_W;
        int z = o >> 14, rem = o & 16383;
        int n = rem >> 7, k = rem & 127;
        v = Wp[n * 256 + z * 128 + k];
        H = g_wph; L = g_wpl;
    }
    float h = to_tf32(v);
    H[o] = h;
    L[o] = to_tf32(v - h);
}

// ---------------------------------------------------------------------------
// GEMM core: BM=32, BN=64, BK=32, 256 threads = 8 warps (2m x 4n),
// NBUF=4 cp.async ring, ONE barrier per chunk.
// ---------------------------------------------------------------------------
#define SPAD 36
#define GA_SZ (32 * SPAD)   // 1152
#define GB_SZ (64 * SPAD)   // 2304
#define OFF_AH(b) ((b) * GA_SZ)
#define OFF_AL(b) (4 * GA_SZ + (b) * GA_SZ)
#define OFF_BH(b) (8 * GA_SZ + (b) * GB_SZ)
#define OFF_BL(b) (8 * GA_SZ + 4 * GB_SZ + (b) * GB_SZ)
#define GEMM_SMEM_FLOATS (8 * GA_SZ + 8 * GB_SZ)   // 27648 floats = 110592 B

__device__ __forceinline__ void mma_chunk32(float acc[2][4],
                                            const float* Ah, const float* Al,
                                            const float* Bh, const float* Bl,
                                            int wm, int wn, int gid, int ctid) {
    const u32* AhU = (const u32*)Ah; const u32* AlU = (const u32*)Al;
    const u32* BhU = (const u32*)Bh; const u32* BlU = (const u32*)Bl;
    const int ar0 = (wm * 16 + gid) * SPAD;
    const int ar1 = (wm * 16 + gid + 8) * SPAD;
#pragma unroll
    for (int kk = 0; kk < 4; kk++) {
        int k8 = kk * 8;
        u32 ah[4], al[4], bh[2][2], bl[2][2];
        ah[0] = AhU[ar0 + k8 + ctid];     ah[1] = AhU[ar1 + k8 + ctid];
        ah[2] = AhU[ar0 + k8 + ctid + 4]; ah[3] = AhU[ar1 + k8 + ctid + 4];
        al[0] = AlU[ar0 + k8 + ctid];     al[1] = AlU[ar1 + k8 + ctid];
        al[2] = AlU[ar0 + k8 + ctid + 4]; al[3] = AlU[ar1 + k8 + ctid + 4];
#pragma unroll
        for (int nf = 0; nf < 2; nf++) {
            int r = (wn * 16 + nf * 8 + gid) * SPAD;
            bh[nf][0] = BhU[r + k8 + ctid];
            bh[nf][1] = BhU[r + k8 + ctid + 4];
            bl[nf][0] = BlU[r + k8 + ctid];
            bl[nf][1] = BlU[r + k8 + ctid + 4];
        }
#pragma unroll
        for (int nf = 0; nf < 2; nf++) {
            mma_tf32(acc[nf], ah, bh[nf]);
            mma_tf32(acc[nf], ah, bl[nf]);
            mma_tf32(acc[nf], al, bh[nf]);
        }
    }
}

// ---------------------------------------------------------------------------
// Stage 1: Xc(2048 x 256) = leaky(x @ [W1;W2]^T + bias) -> hi/lo planes
// grid (64, 4).
// ---------------------------------------------------------------------------
__global__ __launch_bounds__(256)
void stage1_mma(const float* __restrict__ b1, const float* __restrict__ b2)
{
    extern __shared__ __align__(16) float gsm[];
    const u32 sb = (u32)__cvta_generic_to_shared(gsm);

    const int t = threadIdx.x;
    const int lane = t & 31, warp = t >> 5;
    const int wm = warp >> 2, wn = warp & 3;
    const int gid = lane >> 2, ctid = lane & 3;
    const int m0 = blockIdx.x * 32;
    const int n0 = blockIdx.y * 64;

    const int arI = t >> 3, ak = (t & 7) * 4;   // A: 32 rows x 8 thr
    const int brI = t >> 2, bk = (t & 3) * 8;   // B: 64 rows x 4 thr (2 f4)

    const float* aH = g_xh + (size_t)(m0 + arI) * TDIM + ak;
    const float* aL = g_xl + (size_t)(m0 + arI) * TDIM + ak;
    const float* bH = g_wh + (size_t)(n0 + brI) * TDIM + bk;
    const float* bL = g_wl + (size_t)(n0 + brI) * TDIM + bk;
    const u32 sAH = sb + (arI * SPAD + ak) * 4;
    const u32 sAL = sAH + 4 * GA_SZ * 4;
    const u32 sBH = sb + (8 * GA_SZ + brI * SPAD + bk) * 4;
    const u32 sBL = sBH + 4 * GB_SZ * 4;

    float acc[2][4] = {};
    const int nt = TDIM / 32;   // 9

#define S1_ISSUE(ch, buf) do {                                   \
        int kc_ = (ch) * 32;                                     \
        cpa16(sAH + (buf) * GA_SZ * 4, aH + kc_);                \
        cpa16(sAL + (buf) * GA_SZ * 4, aL + kc_);                \
        cpa16(sBH + (buf) * GB_SZ * 4, bH + kc_);                \
        cpa16(sBH + (buf) * GB_SZ * 4 + 16, bH + kc_ + 4);       \
        cpa16(sBL + (buf) * GB_SZ * 4, bL + kc_);                \
        cpa16(sBL + (buf) * GB_SZ * 4 + 16, bL + kc_ + 4);       \
        cp_commit();                                             \
    } while (0)

    S1_ISSUE(0, 0);
    S1_ISSUE(1, 1);
    for (int ti = 0; ti < nt; ti++) {
        if (ti + 2 < nt) { S1_ISSUE(ti + 2, (ti + 2) & 3); cp_wait<2>(); }
        else if (ti + 1 < nt) cp_wait<1>();
        else cp_wait<0>();
        __syncthreads();
        int cur = ti & 3;
        mma_chunk32(acc, gsm + OFF_AH(cur), gsm + OFF_AL(cur),
                    gsm + OFF_BH(cur), gsm + OFF_BL(cur), wm, wn, gid, ctid);
    }
#undef S1_ISSUE

    const float* bias = (n0 < 128) ? b1 : b2;
    const int bc0 = (n0 < 128) ? n0 : n0 - 128;
    const int row = m0 + wm * 16 + gid;
#pragma unroll
    for (int nf = 0; nf < 2; nf++) {
        int col = n0 + wn * 16 + nf * 8 + 2 * ctid;     // combined col
        int bcol = bc0 + wn * 16 + nf * 8 + 2 * ctid;
        float v0 = acc[nf][0] + bias[bcol];
        float v1 = acc[nf][1] + bias[bcol + 1];
        float v2 = acc[nf][2] + bias[bcol];
        float v3 = acc[nf][3] + bias[bcol + 1];
        v0 = fmaxf(v0, 0.2f * v0); v1 = fmaxf(v1, 0.2f * v1);
        v2 = fmaxf(v2, 0.2f * v2); v3 = fmaxf(v3, 0.2f * v3);
        float h0 = to_tf32(v0), h1 = to_tf32(v1), h2 = to_tf32(v2), h3 = to_tf32(v3);
        *(float2*)&g_Xh[(size_t)row * XCOLS + col]       = make_float2(h0, h1);
        *(float2*)&g_Xh[(size_t)(row + 8) * XCOLS + col] = make_float2(h2, h3);
        *(float2*)&g_Xl[(size_t)row * XCOLS + col]       = make_float2(to_tf32(v0 - h0), to_tf32(v1 - h1));
        *(float2*)&g_Xl[(size_t)(row + 8) * XCOLS + col] = make_float2(to_tf32(v2 - h2), to_tf32(v3 - h3));
    }
}

// ---------------------------------------------------------------------------
// Stage 2: z=0: S1 = X1 @ Wp_a^T ; z=1: S2P = X2 @ Wp_b^T + bp
// grid (64, 2, 2).
// ---------------------------------------------------------------------------
__global__ __launch_bounds__(256)
void stage2_mma(const float* __restrict__ bp)
{
    extern __shared__ __align__(16) float gsm[];
    const u32 sb = (u32)__cvta_generic_to_shared(gsm);

    const int t = threadIdx.x;
    const int lane = t & 31, warp = t >> 5;
    const int wm = warp >> 2, wn = warp & 3;
    const int gid = lane >> 2, ctid = lane & 3;
    const int m0 = blockIdx.x * 32;
    const int n0 = blockIdx.y * 64;
    const int z  = blockIdx.z;

    const int arI = t >> 3, ak = (t & 7) * 4;
    const int brI = t >> 2, bk = (t & 3) * 8;

    const float* aH = g_Xh + (size_t)(m0 + arI) * XCOLS + z * 128 + ak;
    const float* aL = g_Xl + (size_t)(m0 + arI) * XCOLS + z * 128 + ak;
    const float* bH = g_wph + (size_t)z * 16384 + (size_t)(n0 + brI) * 128 + bk;
    const float* bL = g_wpl + (size_t)z * 16384 + (size_t)(n0 + brI) * 128 + bk;
    const u32 sAH = sb + (arI * SPAD + ak) * 4;
    const u32 sAL = sAH + 4 * GA_SZ * 4;
    const u32 sBH = sb + (8 * GA_SZ + brI * SPAD + bk) * 4;
    const u32 sBL = sBH + 4 * GB_SZ * 4;

    float acc[2][4] = {};
    const int nt = LDIM / 32;   // 4

#define S2_ISSUE(ch, buf) do {                                   \
        int kc_ = (ch) * 32;                                     \
        cpa16(sAH + (buf) * GA_SZ * 4, aH + kc_);                \
        cpa16(sAL + (buf) * GA_SZ * 4, aL + kc_);                \
        cpa16(sBH + (buf) * GB_SZ * 4, bH + kc_);                \
        cpa16(sBH + (buf) * GB_SZ * 4 + 16, bH + kc_ + 4);       \
        cpa16(sBL + (buf) * GB_SZ * 4, bL + kc_);                \
        cpa16(sBL + (buf) * GB_SZ * 4 + 16, bL + kc_ + 4);       \
        cp_commit();                                             \
    } while (0)

    S2_ISSUE(0, 0);
    S2_ISSUE(1, 1);
    for (int ti = 0; ti < nt; ti++) {
        if (ti + 2 < nt) { S2_ISSUE(ti + 2, (ti + 2) & 3); cp_wait<2>(); }
        else if (ti + 1 < nt) cp_wait<1>();
        else cp_wait<0>();
        __syncthreads();
        int cur = ti & 3;
        mma_chunk32(acc, gsm + OFF_AH(cur), gsm + OFF_AL(cur),
                    gsm + OFF_BH(cur), gsm + OFF_BL(cur), wm, wn, gid, ctid);
    }
#undef S2_ISSUE

    float* OUT = z ? g_S2P : g_S1;
    const int row = m0 + wm * 16 + gid;
#pragma unroll
    for (int nf = 0; nf < 2; nf++) {
        int col = n0 + wn * 16 + nf * 8 + 2 * ctid;
        float bv0 = z ? bp[col] : 0.f;
        float bv1 = z ? bp[col + 1] : 0.f;
        *(float2*)&OUT[(size_t)row * LDIM + col]       = make_float2(acc[nf][0] + bv0, acc[nf][1] + bv1);
        *(float2*)&OUT[(size_t)(row + 8) * LDIM + col] = make_float2(acc[nf][2] + bv0, acc[nf][3] + bv1);
    }
}

// ---------------------------------------------------------------------------
// Fused pairwise + finalize (unchanged — known good).
// ---------------------------------------------------------------------------
#define SR2 65   // u64 per row (64 + 1 pad)
#define SM_S2   16640
#define SM_C1   24960
#define SM_C2   25024
#define SM_ROWF 50176
#define SM_U64_TOTAL 25280      // 202,240 bytes

__global__ __launch_bounds__(512)
void pairwise_final_kernel(const float* __restrict__ S1, const float* __restrict__ S2P,
                           const float* __restrict__ Wb, const float* __restrict__ bb,
                           const float* __restrict__ noise, float* __restrict__ out)
{
    extern __shared__ __align__(16) u64 sm[];
    u64*   s1t  = sm;
    u64*   s2t  = sm + SM_S2;
    u64*   c1   = sm + SM_C1;
    u64*   c2   = sm + SM_C2;
    float* rowA = ((float*)sm) + SM_ROWF;        // [4][64]
    float* rowB = rowA + 256;                    // [4][32]
    float* red  = (float*)sm;                    // aliased after main loop

    const int t  = threadIdx.x;
    const int b  = t >> 7;
    const int tb = t & 127;
    const int tx = tb & 7;
    const int ty = tb >> 3;
    const int i0 = blockIdx.y * 64;
    const int j0 = blockIdx.x * 32;

    if (t < 64) {
        float2 w = ((const float2*)Wb)[t];
        c1[t] = pack2(0.6f * w.x, 0.6f * w.y);
        c2[t] = pack2(0.4f * w.x, 0.4f * w.y);
    }

    const float4* S1v = (const float4*)S1;
    const float4* S2v = (const float4*)S2P;
#pragma unroll
    for (int s = 0; s < 16; s++) {
        int f   = t + s * 512;
        int bb_ = f >> 11;
        int rem = f & 2047;
        int row = rem >> 5;
        int c4  = rem & 31;
        float4 v = S1v[((size_t)bb_ * N_NODES + i0 + row) * 32 + c4];
        float2* d = (float2*)&s1t[(bb_ * 64 + row) * SR2 + c4 * 2];
        d[0] = make_float2(v.x, v.y);
        d[1] = make_float2(v.z, v.w);
    }
#pragma unroll
    for (int s = 0; s < 8; s++) {
        int f   = t + s * 512;
        int bb_ = f >> 10;
        int rem = f & 1023;
        int row = rem >> 5;
        int c4  = rem & 31;
        float4 v = S2v[((size_t)bb_ * N_NODES + j0 + row) * 32 + c4];
        float2* d = (float2*)&s2t[(bb_ * 32 + row) * SR2 + c4 * 2];
        d[0] = make_float2(v.x, v.y);
        d[1] = make_float2(v.z, v.w);
    }
    __syncthreads();

    if (t < 256) {
        const u64* src = s1t + t * SR2;
        u64 a0 = 0, a1 = 0;
#pragma unroll
        for (int q = 0; q < 64; q += 2) {
            a0 = fma2(c1[q],     src[q],     a0);
            a1 = fma2(c1[q + 1], src[q + 1], a1);
        }
        rowA[t] = lo32(a0) + hi32(a0) + lo32(a1) + hi32(a1);
    } else if (t < 384) {
        int r = t - 256;
        const u64* src = s2t + r * SR2;
        u64 a0 = 0, a1 = 0;
#pragma unroll
        for (int q = 0; q < 64; q += 2) {
            a0 = fma2(c1[q],     src[q],     a0);
            a1 = fma2(c1[q + 1], src[q + 1], a1);
        }
        rowB[r] = lo32(a0) + hi32(a0) + lo32(a1) + hi32(a1);
    }
    __syncthreads();

    u64 acc[4][4] = {};
    const u64 MASK = 0x7fffffff7fffffffULL;
    const u64* s1b = s1t + b * 64 * SR2;
    const u64* s2b = s2t + b * 32 * SR2;
#pragma unroll 2
    for (int kk = 0; kk < 64; kk++) {
        u64 cw = c2[kk];
        u64 ra[4], rb[4];
#pragma unroll
        for (int r = 0; r < 4; r++) ra[r] = s1b[(ty + 16 * r) * SR2 + kk];
#pragma unroll
        for (int c = 0; c < 4; c++) rb[c] = s2b[(tx + 8 * c) * SR2 + kk];
#pragma unroll
        for (int r = 0; r < 4; r++)
#pragma unroll
            for (int c = 0; c < 4; c++) {
                u64 v = add2(ra[r], rb[c]);
                acc[r][c] = fma2(cw, v & MASK, acc[r][c]);
            }
    }

    const float bbv = bb[0];
    float sig[4][4];
#pragma unroll
    for (int r = 0; r < 4; r++) {
        float ai = rowA[b * 64 + ty + 16 * r];
#pragma unroll
        for (int c = 0; c < 4; c++) {
            float z = lo32(acc[r][c]) + hi32(acc[r][c])
                    + ai + rowB[b * 32 + tx + 8 * c] + bbv;
            sig[r][c] = 1.f / (1.f + __expf(-z));
        }
    }
    __syncthreads();

#pragma unroll
    for (int r = 0; r < 4; r++)
#pragma unroll
        for (int c = 0; c < 4; c++)
            red[(b * 128 + tb) * 16 + r * 4 + c] = sig[r][c];
    __syncthreads();

#pragma unroll
    for (int e = 0; e < 4; e++) {
        int o = t * 4 + e;
        int i = o >> 5;
        int j = o & 31;
        int ty2 = i & 15, r2 = i >> 4;
        int tx2 = j & 7,  c2_ = j >> 3;
        int base = (ty2 * 8 + tx2) * 16 + r2 * 4 + c2_;
        float p = 0.25f * (red[base] + red[2048 + base]
                         + red[4096 + base] + red[6144 + base]);
        int gi = i0 + i, gj = j0 + j;
        if (gi == gj) p = 0.f;
        float lp = __logf(p + 1e-10f) - __logf(1.0f + (1e-10f - p));
        lp = fminf(fmaxf(lp, -10.f), 10.f);
        float ns = noise[(size_t)gi * N_NODES + gj];
        float lo = __logf(ns) - __logf(1.0f - ns);
        float z = (lp + lo) * 5.0f;
        out[(size_t)gi * N_NODES + gj] = 1.f / (1.f + __expf(-z));
    }
}

// ---------------------------------------------------------------------------
extern "C" void kernel_launch(void* const* d_in, const int* in_sizes, int n_in,
                              void* d_out, int out_size)
{
    const float* x     = (const float*)d_in[0];
    const float* W1    = (const float*)d_in[1];
    const float* b1    = (const float*)d_in[2];
    const float* W2    = (const float*)d_in[3];
    const float* b2    = (const float*)d_in[4];
    const float* Wp    = (const float*)d_in[5];
    const float* bp    = (const float*)d_in[6];
    const float* Wb    = (const float*)d_in[7];
    const float* bb    = (const float*)d_in[8];
    const float* noise = (const float*)d_in[9];
    float* out = (float*)d_out;

    float *S1, *S2P;
    cudaGetSymbolAddress((void**)&S1,  g_S1);
    cudaGetSymbolAddress((void**)&S2P, g_S2P);

    const size_t gemm_smem = (size_t)GEMM_SMEM_FLOATS * sizeof(float);  // 110592 B
    cudaFuncSetAttribute(stage1_mma, cudaFuncAttributeMaxDynamicSharedMemorySize,
                         (int)gemm_smem);
    cudaFuncSetAttribute(stage2_mma, cudaFuncAttributeMaxDynamicSharedMemorySize,
                         (int)gemm_smem);

    // Stage 0: split inputs/weights into tf32 hi/lo planes
    int tot = N_X + N_W + N_WP;
    prep_split<<<(tot + 255) / 256, 256>>>(x, W1, W2, Wp);

    // Stage 1: Xc = leaky(x @ [W1;W2]^T + bias) -> hi/lo
    stage1_mma<<<dim3(MROWS / 32, 4), 256, gemm_smem>>>(b1, b2);

    // Stage 2: S1 = X1@Wp_a^T, S2P = X2@Wp_b^T + bp
    stage2_mma<<<dim3(MROWS / 32, 2, 2), 256, gemm_smem>>>(bp);

    // Stage 3: fused pairwise + finalize, writes out directly
    size_t smem = (size_t)SM_U64_TOTAL * sizeof(u64);
    cudaFuncSetAttribute(pairwise_final_kernel,
                         cudaFuncAttributeMaxDynamicSharedMemorySize, (int)smem);
    dim3 g3(N_NODES / 32, N_NODES / 64);   // 16 x 8 = 128 blocks
    pairwise_final_kernel<<<g3, dim3(512), smem>>>(S1, S2P, Wb, bb, noise, out);
}

// round 10
// speedup vs baseline: 1.1127x; 1.1127x over previous
#include <cuda_runtime.h>
#include <math.h>

#define N_NODES 512
#define TDIM 288
#define LDIM 128
#define BBATCH 4
#define MROWS (BBATCH * N_NODES)   // 2048

typedef unsigned long long u64;
typedef unsigned int u32;

// ---- packed f32x2 helpers (sm_100+) ----
__device__ __forceinline__ u64 add2(u64 a, u64 b) {
    u64 r; asm("add.rn.f32x2 %0,%1,%2;" : "=l"(r) : "l"(a), "l"(b)); return r;
}
__device__ __forceinline__ u64 fma2(u64 a, u64 b, u64 c) {
    u64 r; asm("fma.rn.f32x2 %0,%1,%2,%3;" : "=l"(r) : "l"(a), "l"(b), "l"(c)); return r;
}
__device__ __forceinline__ float lo32(u64 v) { return __uint_as_float((unsigned)(v & 0xffffffffu)); }
__device__ __forceinline__ float hi32(u64 v) { return __uint_as_float((unsigned)(v >> 32)); }
__device__ __forceinline__ u64 pack2(float x, float y) {
    return ((u64)__float_as_uint(y) << 32) | (u64)__float_as_uint(x);
}

// ---- tf32 helpers ----
__device__ __forceinline__ float to_tf32(float v) {
    u32 r; asm("cvt.rna.tf32.f32 %0,%1;" : "=r"(r) : "f"(v));
    return __uint_as_float(r);
}
__device__ __forceinline__ void mma_tf32(float* d, const u32* a, const u32* b) {
    asm("mma.sync.aligned.m16n8k8.row.col.f32.tf32.tf32.f32 "
        "{%0,%1,%2,%3}, {%4,%5,%6,%7}, {%8,%9}, {%0,%1,%2,%3};"
        : "+f"(d[0]), "+f"(d[1]), "+f"(d[2]), "+f"(d[3])
        : "r"(a[0]), "r"(a[1]), "r"(a[2]), "r"(a[3]), "r"(b[0]), "r"(b[1]));
}

// Scratch (device globals)
__device__ float g_X1[MROWS * LDIM];
__device__ float g_X2[MROWS * LDIM];
__device__ float g_S1[MROWS * LDIM];
__device__ float g_S2P[MROWS * LDIM];
__device__ float g_P[BBATCH * N_NODES * N_NODES];

// ---------------------------------------------------------------------------
// 3xTF32 mma GEMM core (R8 design — proven). BM=32, BN=64, BK=32, 8 warps,
// double-buffered dynamic smem, 2-deep register prefetch, 1 barrier/chunk.
// ---------------------------------------------------------------------------
#define SPAD 36
#define GA_SZ (32 * SPAD)
#define GB_SZ (64 * SPAD)
#define OFF_AH(buf) ((buf) * GA_SZ)
#define OFF_AL(buf) (2 * GA_SZ + (buf) * GA_SZ)
#define OFF_BH(buf) (4 * GA_SZ + (buf) * GB_SZ)
#define OFF_BL(buf) (4 * GA_SZ + 2 * GB_SZ + (buf) * GB_SZ)
#define GEMM_SMEM_FLOATS (4 * GA_SZ + 4 * GB_SZ)   // 13824 floats = 55296 B

__device__ __forceinline__ void split_store(float* H, float* L, int idx4, float4 v) {
    float4 h, l;
    h.x = to_tf32(v.x); l.x = to_tf32(v.x - h.x);
    h.y = to_tf32(v.y); l.y = to_tf32(v.y - h.y);
    h.z = to_tf32(v.z); l.z = to_tf32(v.z - h.z);
    h.w = to_tf32(v.w); l.w = to_tf32(v.w - h.w);
    *(float4*)(H + idx4) = h;
    *(float4*)(L + idx4) = l;
}

__device__ __forceinline__ void mma_chunk32(float acc[2][4],
                                            const float* Ah, const float* Al,
                                            const float* Bh, const float* Bl,
                                            int wm, int wn, int gid, int ctid) {
    const u32* AhU = (const u32*)Ah; const u32* AlU = (const u32*)Al;
    const u32* BhU = (const u32*)Bh; const u32* BlU = (const u32*)Bl;
    const int ar0 = (wm * 16 + gid) * SPAD;
    const int ar1 = (wm * 16 + gid + 8) * SPAD;
#pragma unroll
    for (int kk = 0; kk < 4; kk++) {
        int k8 = kk * 8;
        u32 ah[4], al[4], bh[2][2], bl[2][2];
        ah[0] = AhU[ar0 + k8 + ctid];     ah[1] = AhU[ar1 + k8 + ctid];
        ah[2] = AhU[ar0 + k8 + ctid + 4]; ah[3] = AhU[ar1 + k8 + ctid + 4];
        al[0] = AlU[ar0 + k8 + ctid];     al[1] = AlU[ar1 + k8 + ctid];
        al[2] = AlU[ar0 + k8 + ctid + 4]; al[3] = AlU[ar1 + k8 + ctid + 4];
#pragma unroll
        for (int nf = 0; nf < 2; nf++) {
            int r = (wn * 16 + nf * 8 + gid) * SPAD;
            bh[nf][0] = BhU[r + k8 + ctid];
            bh[nf][1] = BhU[r + k8 + ctid + 4];
            bl[nf][0] = BlU[r + k8 + ctid];
            bl[nf][1] = BlU[r + k8 + ctid + 4];
        }
#pragma unroll
        for (int nf = 0; nf < 2; nf++) {
            mma_tf32(acc[nf], ah, bh[nf]);
            mma_tf32(acc[nf], ah, bl[nf]);
            mma_tf32(acc[nf], al, bh[nf]);
        }
    }
}

// Stage 1: [X1|X2] = leaky(x @ [W1;W2]^T + bias). grid (64, 4).
__global__ __launch_bounds__(256)
void stage1_mma(const float* __restrict__ x,
                const float* __restrict__ W1, const float* __restrict__ W2,
                const float* __restrict__ b1, const float* __restrict__ b2,
                float* __restrict__ X1, float* __restrict__ X2)
{
    extern __shared__ __align__(16) float gsm[];

    const int t = threadIdx.x;
    const int lane = t & 31, warp = t >> 5;
    const int wm = warp >> 2, wn = warp & 3;
    const int gid = lane >> 2, ctid = lane & 3;
    const int m0 = blockIdx.x * 32;
    const int n0 = blockIdx.y * 64;

    const int arI = t >> 3, ak = (t & 7) * 4;
    const int brI = t >> 2, bk = (t & 3) * 8;

    const float* arow = x + (size_t)(m0 + arI) * TDIM + ak;
    const float* wrow = (n0 + brI) < 128
        ? W1 + (size_t)(n0 + brI) * TDIM + bk
        : W2 + (size_t)(n0 + brI - 128) * TDIM + bk;

    float acc[2][4] = {};
    const int nt = TDIM / 32;        // 9

    float4 rA, rB0, rB1;
    rA  = *(const float4*)(arow);
    rB0 = *(const float4*)(wrow);
    rB1 = *(const float4*)(wrow + 4);
    split_store(gsm + OFF_AH(0), gsm + OFF_AL(0), arI * SPAD + ak, rA);
    split_store(gsm + OFF_BH(0), gsm + OFF_BL(0), brI * SPAD + bk, rB0);
    split_store(gsm + OFF_BH(0), gsm + OFF_BL(0), brI * SPAD + bk + 4, rB1);
    rA  = *(const float4*)(arow + 32);
    rB0 = *(const float4*)(wrow + 32);
    rB1 = *(const float4*)(wrow + 36);
    __syncthreads();

    for (int ti = 0; ti < nt; ti++) {
        int cur = ti & 1;
        if (ti + 1 < nt) {
            int nx = cur ^ 1;
            split_store(gsm + OFF_AH(nx), gsm + OFF_AL(nx), arI * SPAD + ak, rA);
            split_store(gsm + OFF_BH(nx), gsm + OFF_BL(nx), brI * SPAD + bk, rB0);
            split_store(gsm + OFF_BH(nx), gsm + OFF_BL(nx), brI * SPAD + bk + 4, rB1);
            if (ti + 2 < nt) {
                int k0 = (ti + 2) * 32;
                rA  = *(const float4*)(arow + k0);
                rB0 = *(const float4*)(wrow + k0);
                rB1 = *(const float4*)(wrow + k0 + 4);
            }
        }
        mma_chunk32(acc, gsm + OFF_AH(cur), gsm + OFF_AL(cur),
                    gsm + OFF_BH(cur), gsm + OFF_BL(cur), wm, wn, gid, ctid);
        __syncthreads();
    }

    const int half = (n0 < 128);
    float* OUT = half ? X1 : X2;
    const float* bias = half ? b1 : b2;
    const int nloc0 = half ? n0 : n0 - 128;
    const int row = m0 + wm * 16 + gid;
#pragma unroll
    for (int nf = 0; nf < 2; nf++) {
        int col = nloc0 + wn * 16 + nf * 8 + 2 * ctid;
        float v0 = acc[nf][0] + bias[col];
        float v1 = acc[nf][1] + bias[col + 1];
        float v2 = acc[nf][2] + bias[col];
        float v3 = acc[nf][3] + bias[col + 1];
        v0 = fmaxf(v0, 0.2f * v0); v1 = fmaxf(v1, 0.2f * v1);
        v2 = fmaxf(v2, 0.2f * v2); v3 = fmaxf(v3, 0.2f * v3);
        *(float2*)&OUT[(size_t)row * LDIM + col]       = make_float2(v0, v1);
        *(float2*)&OUT[(size_t)(row + 8) * LDIM + col] = make_float2(v2, v3);
    }
}

// Stage 2: z=0: S1 = X1 @ Wp_a^T ; z=1: S2P = X2 @ Wp_b^T + bp. grid (64,2,2).
__global__ __launch_bounds__(256)
void stage2_mma(const float* __restrict__ X1, const float* __restrict__ X2,
                const float* __restrict__ Wp, const float* __restrict__ bp,
                float* __restrict__ S1, float* __restrict__ S2P)
{
    extern __shared__ __align__(16) float gsm[];

    const int t = threadIdx.x;
    const int lane = t & 31, warp = t >> 5;
    const int wm = warp >> 2, wn = warp & 3;
    const int gid = lane >> 2, ctid = lane & 3;
    const int m0 = blockIdx.x * 32;
    const int n0 = blockIdx.y * 64;
    const int z  = blockIdx.z;

    const float* A = z ? X2 : X1;
    const int arI = t >> 3, ak = (t & 7) * 4;
    const int brI = t >> 2, bk = (t & 3) * 8;
    const float* arow = A + (size_t)(m0 + arI) * LDIM + ak;
    const float* wrow = Wp + (size_t)(n0 + brI) * (2 * LDIM) + z * LDIM + bk;

    float acc[2][4] = {};
    const int nt = LDIM / 32;        // 4

    float4 rA, rB0, rB1;
    rA  = *(const float4*)(arow);
    rB0 = *(const float4*)(wrow);
    rB1 = *(const float4*)(wrow + 4);
    split_store(gsm + OFF_AH(0), gsm + OFF_AL(0), arI * SPAD + ak, rA);
    split_store(gsm + OFF_BH(0), gsm + OFF_BL(0), brI * SPAD + bk, rB0);
    split_store(gsm + OFF_BH(0), gsm + OFF_BL(0), brI * SPAD + bk + 4, rB1);
    rA  = *(const float4*)(arow + 32);
    rB0 = *(const float4*)(wrow + 32);
    rB1 = *(const float4*)(wrow + 36);
    __syncthreads();

    for (int ti = 0; ti < nt; ti++) {
        int cur = ti & 1;
        if (ti + 1 < nt) {
            int nx = cur ^ 1;
            split_store(gsm + OFF_AH(nx), gsm + OFF_AL(nx), arI * SPAD + ak, rA);
            split_store(gsm + OFF_BH(nx), gsm + OFF_BL(nx), brI * SPAD + bk, rB0);
            split_store(gsm + OFF_BH(nx), gsm + OFF_BL(nx), brI * SPAD + bk + 4, rB1);
            if (ti + 2 < nt) {
                int k0 = (ti + 2) * 32;
                rA  = *(const float4*)(arow + k0);
                rB0 = *(const float4*)(wrow + k0);
                rB1 = *(const float4*)(wrow + k0 + 4);
            }
        }
        mma_chunk32(acc, gsm + OFF_AH(cur), gsm + OFF_AL(cur),
                    gsm + OFF_BH(cur), gsm + OFF_BL(cur), wm, wn, gid, ctid);
        __syncthreads();
    }

    float* OUT = z ? S2P : S1;
    const int row = m0 + wm * 16 + gid;
#pragma unroll
    for (int nf = 0; nf < 2; nf++) {
        int col = n0 + wn * 16 + nf * 8 + 2 * ctid;
        float bv0 = z ? bp[col] : 0.f;
        float bv1 = z ? bp[col + 1] : 0.f;
        *(float2*)&OUT[(size_t)row * LDIM + col]       = make_float2(acc[nf][0] + bv0, acc[nf][1] + bv1);
        *(float2*)&OUT[(size_t)(row + 8) * LDIM + col] = make_float2(acc[nf][2] + bv0, acc[nf][3] + bv1);
    }
}

// ---------------------------------------------------------------------------
// Pairwise (split per batch plane): grid (16 jx, 8 iy, 4 b), 128 threads.
// Each block: one b, 64i x 32j tile. smem ~50KB -> 4 blocks/SM.
//   P[b,i,j] = sigmoid(A_i + B_j + bb + sum_l (0.4 Wb_l)|S1[b,i,l]+S2P[b,j,l]|)
// ---------------------------------------------------------------------------
#define SR2 65   // u64 per row (64 + 1 pad)
// u64 layout: s1t[64*65]=4160 | s2t[32*65]=2080 | c1[64] | c2[64] | rows(96f=48)
#define PW_S2   4160
#define PW_C1   6240
#define PW_C2   6304
#define PW_ROWF 12736           // float index of rowA (= 6368 u64 * 2)
#define PW_U64_TOTAL 6416       // 51,328 bytes

__global__ __launch_bounds__(128)
void pairwise_kernel(const float* __restrict__ S1, const float* __restrict__ S2P,
                     const float* __restrict__ Wb, const float* __restrict__ bb,
                     float* __restrict__ P)
{
    extern __shared__ __align__(16) u64 sm[];
    u64*   s1t  = sm;
    u64*   s2t  = sm + PW_S2;
    u64*   c1   = sm + PW_C1;
    u64*   c2   = sm + PW_C2;
    float* rowA = ((float*)sm) + PW_ROWF;        // [64]
    float* rowB = rowA + 64;                     // [32]

    const int t  = threadIdx.x;
    const int tx = t & 7;           // j micro col 0..7
    const int ty = t >> 3;          // i micro row 0..15
    const int j0 = blockIdx.x * 32;
    const int i0 = blockIdx.y * 64;
    const int b  = blockIdx.z;

    if (t < 64) {
        float2 w = ((const float2*)Wb)[t];
        c1[t] = pack2(0.6f * w.x, 0.6f * w.y);
        c2[t] = pack2(0.4f * w.x, 0.4f * w.y);
    }

    const float4* S1v = (const float4*)(S1  + ((size_t)b * N_NODES + i0) * LDIM);
    const float4* S2v = (const float4*)(S2P + ((size_t)b * N_NODES + j0) * LDIM);
#pragma unroll
    for (int s = 0; s < 16; s++) {
        int f   = t + s * 128;          // 0..2047
        int row = f >> 5;
        int c4  = f & 31;
        float4 v = S1v[row * 32 + c4];
        float2* d = (float2*)&s1t[row * SR2 + c4 * 2];
        d[0] = make_float2(v.x, v.y);
        d[1] = make_float2(v.z, v.w);
    }
#pragma unroll
    for (int s = 0; s < 8; s++) {
        int f   = t + s * 128;          // 0..1023
        int row = f >> 5;
        int c4  = f & 31;
        float4 v = S2v[row * 32 + c4];
        float2* d = (float2*)&s2t[row * SR2 + c4 * 2];
        d[0] = make_float2(v.x, v.y);
        d[1] = make_float2(v.z, v.w);
    }
    __syncthreads();

    // separable linear parts: rowA (2 thr/row over 128 thr), rowB (thr<64)
    {
        int row  = t >> 1;
        int half = t & 1;
        const u64* src = s1t + row * SR2 + half * 32;
        const u64* cc  = c1 + half * 32;
        u64 a0 = 0, a1 = 0;
#pragma unroll
        for (int q = 0; q < 32; q += 2) {
            a0 = fma2(cc[q],     src[q],     a0);
            a1 = fma2(cc[q + 1], src[q + 1], a1);
        }
        float s = lo32(a0) + hi32(a0) + lo32(a1) + hi32(a1);
        s += __shfl_xor_sync(0xffffffffu, s, 1);
        if (half == 0) rowA[row] = s;
    }
    if (t < 64) {
        int row  = t >> 1;
        int half = t & 1;
        const u64* src = s2t + row * SR2 + half * 32;
        const u64* cc  = c1 + half * 32;
        u64 a0 = 0, a1 = 0;
#pragma unroll
        for (int q = 0; q < 32; q += 2) {
            a0 = fma2(cc[q],     src[q],     a0);
            a1 = fma2(cc[q + 1], src[q + 1], a1);
        }
        float s = lo32(a0) + hi32(a0) + lo32(a1) + hi32(a1);
        s += __shfl_xor_sync(0xffffffffu, s, 1);
        if (half == 0) rowB[row] = s;
    }
    __syncthreads();

    u64 acc[4][4] = {};
    const u64 MASK = 0x7fffffff7fffffffULL;
#pragma unroll 2
    for (int kk = 0; kk < 64; kk++) {
        u64 cw = c2[kk];
        u64 ra[4], rb[4];
#pragma unroll
        for (int r = 0; r < 4; r++) ra[r] = s1t[(ty + 16 * r) * SR2 + kk];
#pragma unroll
        for (int c = 0; c < 4; c++) rb[c] = s2t[(tx + 8 * c) * SR2 + kk];
#pragma unroll
        for (int r = 0; r < 4; r++)
#pragma unroll
            for (int c = 0; c < 4; c++) {
                u64 v = add2(ra[r], rb[c]);
                acc[r][c] = fma2(cw, v & MASK, acc[r][c]);
            }
    }

    const float bbv = bb[0];
    float* Pb = P + (size_t)b * N_NODES * N_NODES;
#pragma unroll
    for (int r = 0; r < 4; r++) {
        int i = i0 + ty + 16 * r;
        float ai = rowA[ty + 16 * r];
#pragma unroll
        for (int c = 0; c < 4; c++) {
            int j = j0 + tx + 8 * c;
            float z = lo32(acc[r][c]) + hi32(acc[r][c])
                    + ai + rowB[tx + 8 * c] + bbv;
            Pb[(size_t)i * N_NODES + j] = 1.f / (1.f + __expf(-z));
        }
    }
}

// ---------------------------------------------------------------------------
// Finalize: p = mean_b P -> diag mask -> clamped logit -> +logistic(noise)
//           -> sigmoid(/0.2). One float4 per thread; 512 blocks x 128 thr.
// ---------------------------------------------------------------------------
__global__ __launch_bounds__(128)
void finalize_kernel(const float* __restrict__ P, const float* __restrict__ noise,
                     float* __restrict__ out)
{
    int q = blockIdx.x * 128 + threadIdx.x;   // float4 index, 0..65535
    const int PL4 = N_NODES * N_NODES / 4;
    float4 p0 = ((const float4*)P)[q];
    float4 p1 = ((const float4*)P)[q + PL4];
    float4 p2 = ((const float4*)P)[q + 2 * PL4];
    float4 p3 = ((const float4*)P)[q + 3 * PL4];
    float4 ns = ((const float4*)noise)[q];

    int idx0 = q * 4;
    int i = idx0 >> 9;
    int jbase = idx0 & (N_NODES - 1);

    float pv[4] = { 0.25f * (p0.x + p1.x + p2.x + p3.x),
                    0.25f * (p0.y + p1.y + p2.y + p3.y),
                    0.25f * (p0.z + p1.z + p2.z + p3.z),
                    0.25f * (p0.w + p1.w + p2.w + p3.w) };
    float nv[4] = { ns.x, ns.y, ns.z, ns.w };
    float4 o;
    float* op = (float*)&o;
#pragma unroll
    for (int e = 0; e < 4; e++) {
        float p = pv[e];
        if (i == jbase + e) p = 0.f;
        float lp = __logf(p + 1e-10f) - __logf(1.0f + (1e-10f - p));
        lp = fminf(fmaxf(lp, -10.f), 10.f);
        float lo = __logf(nv[e]) - __logf(1.0f - nv[e]);
        float z = (lp + lo) * 5.0f;     // / TEMPERATURE (0.2)
        op[e] = 1.f / (1.f + __expf(-z));
    }
    ((float4*)out)[q] = o;
}

// ---------------------------------------------------------------------------
extern "C" void kernel_launch(void* const* d_in, const int* in_sizes, int n_in,
                              void* d_out, int out_size)
{
    const float* x     = (const float*)d_in[0];
    const float* W1    = (const float*)d_in[1];
    const float* b1    = (const float*)d_in[2];
    const float* W2    = (const float*)d_in[3];
    const float* b2    = (const float*)d_in[4];
    const float* Wp    = (const float*)d_in[5];
    const float* bp    = (const float*)d_in[6];
    const float* Wb    = (const float*)d_in[7];
    const float* bb    = (const float*)d_in[8];
    const float* noise = (const float*)d_in[9];
    float* out = (float*)d_out;

    float *X1, *X2, *S1, *S2P, *P;
    cudaGetSymbolAddress((void**)&X1,  g_X1);
    cudaGetSymbolAddress((void**)&X2,  g_X2);
    cudaGetSymbolAddress((void**)&S1,  g_S1);
    cudaGetSymbolAddress((void**)&S2P, g_S2P);
    cudaGetSymbolAddress((void**)&P,   g_P);

    const size_t gemm_smem = (size_t)GEMM_SMEM_FLOATS * sizeof(float);  // 55296 B
    cudaFuncSetAttribute(stage1_mma, cudaFuncAttributeMaxDynamicSharedMemorySize,
                         (int)gemm_smem);
    cudaFuncSetAttribute(stage2_mma, cudaFuncAttributeMaxDynamicSharedMemorySize,
                         (int)gemm_smem);

    // Stage 1: [X1|X2] = leaky(x @ [W1;W2]^T + bias)   (3xTF32 mma)
    stage1_mma<<<dim3(MROWS / 32, 4), 256, gemm_smem>>>(x, W1, W2, b1, b2, X1, X2);

    // Stage 2: S1 = X1@Wp_a^T, S2P = X2@Wp_b^T + bp    (3xTF32 mma)
    stage2_mma<<<dim3(MROWS / 32, 2, 2), 256, gemm_smem>>>(X1, X2, Wp, bp, S1, S2P);

    // Stage 3: pairwise sigmoid planes (one b per block; 512 blocks)
    size_t pw_smem = (size_t)PW_U64_TOTAL * sizeof(u64);   // 51,328 B
    cudaFuncSetAttribute(pairwise_kernel,
                         cudaFuncAttributeMaxDynamicSharedMemorySize, (int)pw_smem);
    dim3 g3(N_NODES / 32, N_NODES / 64, BBATCH);   // 16 x 8 x 4 = 512
    pairwise_kernel<<<g3, dim3(128), pw_smem>>>(S1, S2P, Wb, bb, P);

    // Stage 4: epilogue
    finalize_kernel<<<N_NODES * N_NODES / 4 / 128, 128>>>(P, noise, out);
}